// round 1
// baseline (speedup 1.0000x reference)
#include <cuda_runtime.h>
#include <math.h>

// ---------------------------------------------------------------------------
// CrossModalAttention: fp32 baseline pipeline
//   Q = query@Wq^T+bq ; K = key@Wk^T+bk ; V = value@Wv^T+bv
//   S = (Q K^T) * temperature  (per head)
//   P = softmax(S)             (also an output!)
//   ctx = P @ V
//   o = ctx @ Wo^T + bo
//   out = LayerNorm(o + query)
// Shapes fixed: B=2, S=2048, HIDDEN=1024, HEADS=16, HDIM=64.
// ---------------------------------------------------------------------------

#define HIDDEN_ 1024
#define HEADS_  16
#define HDIM_   64
#define BATCH_  2
#define SEQ_    2048
#define MTOT_   (BATCH_*SEQ_)                 // 4096

static const long long LN_N  = (long long)MTOT_ * HIDDEN_;               // 4,194,304
static const long long ATT_N = (long long)BATCH_ * HEADS_ * SEQ_ * SEQ_; // 134,217,728

// Scratch (allocation-free rule: __device__ globals)
__device__ float g_Q[(size_t)MTOT_ * HIDDEN_];
__device__ float g_K[(size_t)MTOT_ * HIDDEN_];
__device__ float g_V[(size_t)MTOT_ * HIDDEN_];
__device__ float g_ctx[(size_t)MTOT_ * HIDDEN_];
__device__ float g_o[(size_t)MTOT_ * HIDDEN_];
__device__ float g_P[(size_t)BATCH_ * HEADS_ * SEQ_ * SEQ_];  // fallback if attn not in d_out

// ---------------------------------------------------------------------------
// Generic tiled GEMM.
//   TB=true :  C[m,n] = alpha * sum_k A[m,k]*B[n,k]  + bias[n]   (A @ B^T)
//   TB=false:  C[m,n] = alpha * sum_k A[m,k]*B[k,n]  + bias[n]   (A @ B)
// Batched over blockIdx.z with split offsets: off = (z/zdiv)*O1 + (z%zdiv)*O2.
// All dims assumed multiples of tile sizes (true for this problem).
// Threads: 256 (16x16). Thread (tx,ty) owns rows {ty+16i}, cols {tx+16j}
// (strided micro-tile -> conflict-free LDS reads, coalesced STG).
// ---------------------------------------------------------------------------
template <int BM, int BN, int BK, int TM, int TN, bool TB>
__global__ void __launch_bounds__(256)
gemm_kernel(const float* __restrict__ A, const float* __restrict__ Bm,
            const float* __restrict__ bias, const float* __restrict__ alphaP,
            float* __restrict__ C,
            int K, int lda, int ldb, int ldc, int zdiv,
            long long aO1, long long aO2, long long bO1, long long bO2,
            long long cO1, long long cO2)
{
    __shared__ float As[BK][BM + 1];
    __shared__ float Bs[BK][BN + 1];

    const int z = blockIdx.z;
    A  += (long long)(z / zdiv) * aO1 + (long long)(z % zdiv) * aO2;
    Bm += (long long)(z / zdiv) * bO1 + (long long)(z % zdiv) * bO2;
    C  += (long long)(z / zdiv) * cO1 + (long long)(z % zdiv) * cO2;

    const int tid = threadIdx.x;
    const int tx = tid & 15;
    const int ty = tid >> 4;
    const int row0 = blockIdx.y * BM;
    const int col0 = blockIdx.x * BN;

    float acc[TM][TN];
#pragma unroll
    for (int i = 0; i < TM; ++i)
#pragma unroll
        for (int j = 0; j < TN; ++j) acc[i][j] = 0.0f;

    for (int k0 = 0; k0 < K; k0 += BK) {
        // Load A tile: [BM rows] x [BK k]; k contiguous in gmem.
#pragma unroll
        for (int it = 0; it < (BM * BK) / 256; ++it) {
            int i = tid + it * 256;
            int r = i / BK, c = i % BK;
            As[c][r] = A[(size_t)(row0 + r) * lda + (k0 + c)];
        }
        // Load B tile.
        if (TB) {
#pragma unroll
            for (int it = 0; it < (BN * BK) / 256; ++it) {
                int i = tid + it * 256;
                int r = i / BK, c = i % BK;
                Bs[c][r] = Bm[(size_t)(col0 + r) * ldb + (k0 + c)];
            }
        } else {
#pragma unroll
            for (int it = 0; it < (BN * BK) / 256; ++it) {
                int i = tid + it * 256;
                int n = i % BN, c = i / BN;
                Bs[c][n] = Bm[(size_t)(k0 + c) * ldb + (col0 + n)];
            }
        }
        __syncthreads();

#pragma unroll
        for (int k = 0; k < BK; ++k) {
            float a[TM], b[TN];
#pragma unroll
            for (int i = 0; i < TM; ++i) a[i] = As[k][ty + 16 * i];
#pragma unroll
            for (int j = 0; j < TN; ++j) b[j] = Bs[k][tx + 16 * j];
#pragma unroll
            for (int i = 0; i < TM; ++i)
#pragma unroll
                for (int j = 0; j < TN; ++j) acc[i][j] = fmaf(a[i], b[j], acc[i][j]);
        }
        __syncthreads();
    }

    const float alpha = alphaP ? *alphaP : 1.0f;
#pragma unroll
    for (int j = 0; j < TN; ++j) {
        const int c = col0 + tx + 16 * j;
        const float bz = bias ? bias[c] : 0.0f;
#pragma unroll
        for (int i = 0; i < TM; ++i) {
            const int r = row0 + ty + 16 * i;
            C[(size_t)r * ldc + c] = acc[i][j] * alpha + bz;
        }
    }
}

// ---------------------------------------------------------------------------
// In-place row softmax over 2048 columns. One 256-thread block per row.
// ---------------------------------------------------------------------------
__global__ void __launch_bounds__(256)
softmax_kernel(float* __restrict__ P)
{
    __shared__ float red[8];
    __shared__ float bc;

    const size_t row = blockIdx.x;
    float* p = P + row * (size_t)SEQ_;
    const int tid = threadIdx.x;
    const int lane = tid & 31, wid = tid >> 5;

    float v[8];
#pragma unroll
    for (int u = 0; u < 8; ++u) v[u] = p[tid + 256 * u];

    // max reduce
    float m = v[0];
#pragma unroll
    for (int u = 1; u < 8; ++u) m = fmaxf(m, v[u]);
#pragma unroll
    for (int o = 16; o; o >>= 1) m = fmaxf(m, __shfl_xor_sync(0xffffffffu, m, o));
    if (lane == 0) red[wid] = m;
    __syncthreads();
    if (wid == 0) {
        float t = (lane < 8) ? red[lane] : -INFINITY;
#pragma unroll
        for (int o = 16; o; o >>= 1) t = fmaxf(t, __shfl_xor_sync(0xffffffffu, t, o));
        if (lane == 0) bc = t;
    }
    __syncthreads();
    m = bc;

    // exp + sum reduce
    float s = 0.0f;
#pragma unroll
    for (int u = 0; u < 8; ++u) { v[u] = __expf(v[u] - m); s += v[u]; }
#pragma unroll
    for (int o = 16; o; o >>= 1) s += __shfl_xor_sync(0xffffffffu, s, o);
    __syncthreads();                 // red/bc reuse safety
    if (lane == 0) red[wid] = s;
    __syncthreads();
    if (wid == 0) {
        float t = (lane < 8) ? red[lane] : 0.0f;
#pragma unroll
        for (int o = 16; o; o >>= 1) t += __shfl_xor_sync(0xffffffffu, t, o);
        if (lane == 0) bc = t;
    }
    __syncthreads();
    const float inv = 1.0f / bc;
#pragma unroll
    for (int u = 0; u < 8; ++u) p[tid + 256 * u] = v[u] * inv;
}

// ---------------------------------------------------------------------------
// Fused residual + LayerNorm over 1024 columns. One 256-thread block per row.
// ---------------------------------------------------------------------------
__global__ void __launch_bounds__(256)
ln_kernel(const float* __restrict__ o, const float* __restrict__ resid,
          const float* __restrict__ gamma, const float* __restrict__ beta,
          float* __restrict__ out)
{
    __shared__ float red1[8], red2[8];
    __shared__ float bmean, binv;

    const size_t row = blockIdx.x;
    const int tid = threadIdx.x;
    const int lane = tid & 31, wid = tid >> 5;
    const float* po = o + row * HIDDEN_;
    const float* pr = resid + row * HIDDEN_;

    float x[4];
    float s = 0.0f, s2 = 0.0f;
#pragma unroll
    for (int u = 0; u < 4; ++u) {
        const int idx = tid + 256 * u;
        x[u] = po[idx] + pr[idx];
        s += x[u];
        s2 += x[u] * x[u];
    }
#pragma unroll
    for (int of = 16; of; of >>= 1) {
        s  += __shfl_xor_sync(0xffffffffu, s,  of);
        s2 += __shfl_xor_sync(0xffffffffu, s2, of);
    }
    if (lane == 0) { red1[wid] = s; red2[wid] = s2; }
    __syncthreads();
    if (wid == 0) {
        float t1 = (lane < 8) ? red1[lane] : 0.0f;
        float t2 = (lane < 8) ? red2[lane] : 0.0f;
#pragma unroll
        for (int of = 16; of; of >>= 1) {
            t1 += __shfl_xor_sync(0xffffffffu, t1, of);
            t2 += __shfl_xor_sync(0xffffffffu, t2, of);
        }
        if (lane == 0) {
            const float mean = t1 * (1.0f / HIDDEN_);
            const float var  = t2 * (1.0f / HIDDEN_) - mean * mean;
            bmean = mean;
            binv  = rsqrtf(var + 1e-5f);
        }
    }
    __syncthreads();
    const float mean = bmean, inv = binv;
#pragma unroll
    for (int u = 0; u < 4; ++u) {
        const int idx = tid + 256 * u;
        out[row * HIDDEN_ + idx] = (x[u] - mean) * inv * gamma[idx] + beta[idx];
    }
}

// ---------------------------------------------------------------------------
extern "C" void kernel_launch(void* const* d_in, const int* in_sizes, int n_in,
                              void* d_out, int out_size)
{
    const float* query = (const float*)d_in[0];
    const float* key_  = (const float*)d_in[1];
    const float* value = (const float*)d_in[2];
    const float* Wq = (const float*)d_in[3];
    const float* bq = (const float*)d_in[4];
    const float* Wk = (const float*)d_in[5];
    const float* bk = (const float*)d_in[6];
    const float* Wv = (const float*)d_in[7];
    const float* bv = (const float*)d_in[8];
    const float* Wo = (const float*)d_in[9];
    const float* bo = (const float*)d_in[10];
    const float* gamma = (const float*)d_in[11];
    const float* beta  = (const float*)d_in[12];
    const float* temp  = (const float*)d_in[13];

    float* out_ln = (float*)d_out;
    float* pP;
    float *pQ, *pK, *pV, *pCtx, *pO;
    cudaGetSymbolAddress((void**)&pQ,   g_Q);
    cudaGetSymbolAddress((void**)&pK,   g_K);
    cudaGetSymbolAddress((void**)&pV,   g_V);
    cudaGetSymbolAddress((void**)&pCtx, g_ctx);
    cudaGetSymbolAddress((void**)&pO,   g_o);
    if ((long long)out_size >= LN_N + ATT_N) {
        pP = out_ln + LN_N;           // attn_weights are part of the output
    } else {
        cudaGetSymbolAddress((void**)&pP, g_P);
    }

    const long long sQKV = (long long)SEQ_ * HIDDEN_;   // per-batch stride in Q/K/V
    const long long sPP  = (long long)SEQ_ * SEQ_;      // per-head stride in P

    // --- Projections: X @ W^T + b  -> [4096, 1024]
    {
        dim3 g(HIDDEN_ / 128, MTOT_ / 128, 1);
        gemm_kernel<128,128,16,8,8,true><<<g, 256>>>(query, Wq, bq, nullptr, pQ,
            HIDDEN_, HIDDEN_, HIDDEN_, HIDDEN_, 1, 0,0,0,0,0,0);
        gemm_kernel<128,128,16,8,8,true><<<g, 256>>>(key_,  Wk, bk, nullptr, pK,
            HIDDEN_, HIDDEN_, HIDDEN_, HIDDEN_, 1, 0,0,0,0,0,0);
        gemm_kernel<128,128,16,8,8,true><<<g, 256>>>(value, Wv, bv, nullptr, pV,
            HIDDEN_, HIDDEN_, HIDDEN_, HIDDEN_, 1, 0,0,0,0,0,0);
    }

    // --- Scores: per (b,h): S = temp * Q_h @ K_h^T   [2048 x 2048], K=64
    {
        dim3 g(SEQ_ / 128, SEQ_ / 128, BATCH_ * HEADS_);
        gemm_kernel<128,128,32,8,8,true><<<g, 256>>>(pQ, pK, nullptr, temp, pP,
            HDIM_, HIDDEN_, HIDDEN_, SEQ_, HEADS_,
            sQKV, (long long)HDIM_,       // A offsets (b, h)
            sQKV, (long long)HDIM_,       // B offsets
            (long long)HEADS_ * sPP, sPP);// C offsets
    }

    // --- Softmax rows of P (in place); P is the attn_weights output.
    softmax_kernel<<<(unsigned)(BATCH_ * HEADS_ * SEQ_), 256>>>(pP);

    // --- Context: per (b,h): ctx = P @ V_h   [2048 x 64], K=2048
    {
        dim3 g(1, SEQ_ / 128, BATCH_ * HEADS_);
        gemm_kernel<128,64,32,8,4,false><<<g, 256>>>(pP, pV, nullptr, nullptr, pCtx,
            SEQ_, SEQ_, HIDDEN_, HIDDEN_, HEADS_,
            (long long)HEADS_ * sPP, sPP, // A offsets
            sQKV, (long long)HDIM_,       // B offsets
            sQKV, (long long)HDIM_);      // C offsets
    }

    // --- Output projection: o = ctx @ Wo^T + bo
    {
        dim3 g(HIDDEN_ / 128, MTOT_ / 128, 1);
        gemm_kernel<128,128,16,8,8,true><<<g, 256>>>(pCtx, Wo, bo, nullptr, pO,
            HIDDEN_, HIDDEN_, HIDDEN_, HIDDEN_, 1, 0,0,0,0,0,0);
    }

    // --- Residual + LayerNorm
    ln_kernel<<<(unsigned)MTOT_, 256>>>(pO, query, gamma, beta, out_ln);
}

// round 3
// speedup vs baseline: 3.1196x; 3.1196x over previous
#include <cuda_runtime.h>
#include <math.h>
#include <stdint.h>

// ---------------------------------------------------------------------------
// CrossModalAttention on sm_103 (non-'a' PTX target) — tf32 mma.sync pipeline.
//   pre-round inputs/weights to tf32 (RNA)
//   Q/K/V projections  : tf32 HMMA GEMM (A@B^T), epilogue bias + RNA round
//   VT transpose       : per-head V^T for the context GEMM
//   scores             : tf32 HMMA GEMM, raw S -> attn-weights region
//   softmax            : *temperature, in-place, RNA-rounded (= P output)
//   context            : tf32 HMMA GEMM P @ VT^T, epilogue RNA round
//   out projection     : tf32 HMMA GEMM + bias
//   residual + LayerNorm (fp32)
// Shapes fixed: B=2, S=2048, HIDDEN=1024, HEADS=16, HDIM=64.
// ---------------------------------------------------------------------------

#define HIDDEN_ 1024
#define HEADS_  16
#define HDIM_   64
#define BATCH_  2
#define SEQ_    2048
#define MTOT_   (BATCH_*SEQ_)            // 4096

static const long long LN_N  = (long long)MTOT_ * HIDDEN_;               // 4,194,304
static const long long ATT_N = (long long)BATCH_ * HEADS_ * SEQ_ * SEQ_; // 134,217,728

// Scratch (__device__ globals: allocation-free rule)
__device__ float g_Q  [(size_t)MTOT_ * HIDDEN_];
__device__ float g_K  [(size_t)MTOT_ * HIDDEN_];
__device__ float g_V  [(size_t)MTOT_ * HIDDEN_];
__device__ float g_VT [(size_t)BATCH_ * HEADS_ * HDIM_ * SEQ_];
__device__ float g_ctx[(size_t)MTOT_ * HIDDEN_];
__device__ float g_o  [(size_t)MTOT_ * HIDDEN_];
__device__ float g_rq [(size_t)MTOT_ * HIDDEN_];
__device__ float g_rk [(size_t)MTOT_ * HIDDEN_];
__device__ float g_rv [(size_t)MTOT_ * HIDDEN_];
__device__ float g_wq [(size_t)HIDDEN_ * HIDDEN_];
__device__ float g_wk [(size_t)HIDDEN_ * HIDDEN_];
__device__ float g_wv [(size_t)HIDDEN_ * HIDDEN_];
__device__ float g_wo [(size_t)HIDDEN_ * HIDDEN_];
__device__ float g_P  [(size_t)BATCH_ * HEADS_ * SEQ_ * SEQ_];  // fallback

// ---------------------------------------------------------------------------
// PTX helpers (all sm_80+ portable — no 'a'-gated features)
// ---------------------------------------------------------------------------
__device__ __forceinline__ uint32_t smem_u32(const void* p) {
    return (uint32_t)__cvta_generic_to_shared(p);
}
__device__ __forceinline__ float rna_tf32(float x) {
    uint32_t y;
    asm("cvt.rna.tf32.f32 %0, %1;" : "=r"(y) : "f"(x));
    return __uint_as_float(y);
}
__device__ __forceinline__ void cp_async16(uint32_t dst, const void* src) {
    asm volatile("cp.async.cg.shared.global [%0], [%1], 16;" :: "r"(dst), "l"(src));
}
__device__ __forceinline__ void cp_commit() { asm volatile("cp.async.commit_group;" ::: "memory"); }
template <int N>
__device__ __forceinline__ void cp_wait_group() {
    asm volatile("cp.async.wait_group %0;" :: "n"(N) : "memory");
}
// D += A*B, m16n8k8 tf32 (HMMA on tensor pipe)
__device__ __forceinline__ void mma1688(float* d, const uint32_t* a, const uint32_t* b) {
    asm volatile(
        "mma.sync.aligned.m16n8k8.row.col.f32.tf32.tf32.f32 "
        "{%0,%1,%2,%3}, {%4,%5,%6,%7}, {%8,%9}, {%0,%1,%2,%3};"
        : "+f"(d[0]), "+f"(d[1]), "+f"(d[2]), "+f"(d[3])
        : "r"(a[0]), "r"(a[1]), "r"(a[2]), "r"(a[3]), "r"(b[0]), "r"(b[1]));
}

// ---------------------------------------------------------------------------
// tf32 mma.sync GEMM:  C[m,n] = sum_k A[m,k]*B[n,k] (+bias[n]) (opt RNA)
// BM=128, BK=32 floats. 256 threads = 8 warps, WR x WC warp grid.
// SMEM rows padded to 36 floats -> conflict-free 32-bit fragment LDS.
// Batched over blockIdx.z: off = (z/zdiv)*O1 + (z%zdiv)*O2.
// ---------------------------------------------------------------------------
template <int BN, bool ROUND>
__global__ void __launch_bounds__(256)
tc_gemm(const float* __restrict__ A, const float* __restrict__ Bm,
        const float* __restrict__ bias, float* __restrict__ C,
        int K, int lda, int ldb, int ldc, int zdiv,
        long long aO1, long long aO2, long long bO1, long long bO2,
        long long cO1, long long cO2)
{
    constexpr int WR = (BN == 128) ? 2 : 4;      // warp rows
    constexpr int WC = 8 / WR;                   // warp cols
    constexpr int WM = 128 / WR;                 // warp tile M
    constexpr int WN = BN / WC;                  // warp tile N
    constexpr int MT = WM / 16;                  // m-frags per warp
    constexpr int NT = WN / 8;                   // n-frags per warp
    constexpr int LDS_ = 36;                     // padded row stride (floats)
    constexpr int AS_STAGE = 128 * LDS_;
    constexpr int BS_STAGE = BN * LDS_;

    extern __shared__ float sm[];
    float* As = sm;                              // [2][128][36]
    float* Bs = sm + 2 * AS_STAGE;               // [2][BN][36]

    const int z = blockIdx.z;
    A  += (long long)(z / zdiv) * aO1 + (long long)(z % zdiv) * aO2;
    Bm += (long long)(z / zdiv) * bO1 + (long long)(z % zdiv) * bO2;
    C  += (long long)(z / zdiv) * cO1 + (long long)(z % zdiv) * cO2;

    const int tid  = threadIdx.x;
    const int warp = tid >> 5;
    const int lane = tid & 31;
    const int wr = warp % WR, wc = warp / WR;
    const int g = lane >> 2, t = lane & 3;
    const int row0 = blockIdx.y * 128;
    const int col0 = blockIdx.x * BN;

    float acc[MT][NT][4];
#pragma unroll
    for (int i = 0; i < MT; ++i)
#pragma unroll
        for (int j = 0; j < NT; ++j)
#pragma unroll
            for (int q = 0; q < 4; ++q) acc[i][j][q] = 0.0f;

    auto load_tile = [&](int kt) {
        const int st = kt & 1;
        const float* Ag = A + (size_t)row0 * lda + kt * 32;
        float* Ad = As + st * AS_STAGE;
#pragma unroll
        for (int i = 0; i < 4; ++i) {            // 128 rows x 8 chunks / 256 thr
            int id = tid + i * 256;
            int r = id >> 3, c = id & 7;
            cp_async16(smem_u32(Ad + r * LDS_ + c * 4), Ag + (size_t)r * lda + c * 4);
        }
        const float* Bg = Bm + (size_t)col0 * ldb + kt * 32;
        float* Bd = Bs + st * BS_STAGE;
#pragma unroll
        for (int i = 0; i < BN / 32; ++i) {      // BN rows x 8 chunks / 256 thr
            int id = tid + i * 256;
            int r = id >> 3, c = id & 7;
            cp_async16(smem_u32(Bd + r * LDS_ + c * 4), Bg + (size_t)r * ldb + c * 4);
        }
        cp_commit();
    };

    const int T = K >> 5;
    load_tile(0);
    for (int kt = 0; kt < T; ++kt) {
        if (kt + 1 < T) { load_tile(kt + 1); cp_wait_group<1>(); }
        else            { cp_wait_group<0>(); }
        __syncthreads();

        const float* Ab = As + (kt & 1) * AS_STAGE + (wr * WM) * LDS_;
        const float* Bb = Bs + (kt & 1) * BS_STAGE + (wc * WN) * LDS_;
#pragma unroll
        for (int s = 0; s < 4; ++s) {
            const int k0 = s * 8;
            uint32_t a[MT][4], b[NT][2];
#pragma unroll
            for (int i = 0; i < MT; ++i) {
                const float* ap = Ab + (i * 16 + g) * LDS_ + k0 + t;
                a[i][0] = __float_as_uint(ap[0]);
                a[i][1] = __float_as_uint(ap[8 * LDS_]);
                a[i][2] = __float_as_uint(ap[4]);
                a[i][3] = __float_as_uint(ap[8 * LDS_ + 4]);
            }
#pragma unroll
            for (int j = 0; j < NT; ++j) {
                const float* bp = Bb + (j * 8 + g) * LDS_ + k0 + t;
                b[j][0] = __float_as_uint(bp[0]);
                b[j][1] = __float_as_uint(bp[4]);
            }
#pragma unroll
            for (int i = 0; i < MT; ++i)
#pragma unroll
                for (int j = 0; j < NT; ++j)
                    mma1688(acc[i][j], a[i], b[j]);
        }
        __syncthreads();
    }

    // Epilogue: c0/c1 at (row, col..col+1), c2/c3 at (row+8, ...)
#pragma unroll
    for (int i = 0; i < MT; ++i) {
#pragma unroll
        for (int j = 0; j < NT; ++j) {
            const int r = row0 + wr * WM + i * 16 + g;
            const int c = col0 + wc * WN + j * 8 + 2 * t;
            float2 v0 = make_float2(acc[i][j][0], acc[i][j][1]);
            float2 v1 = make_float2(acc[i][j][2], acc[i][j][3]);
            if (bias) {
                const float bx = bias[c], by = bias[c + 1];
                v0.x += bx; v0.y += by;
                v1.x += bx; v1.y += by;
            }
            if (ROUND) {
                v0.x = rna_tf32(v0.x); v0.y = rna_tf32(v0.y);
                v1.x = rna_tf32(v1.x); v1.y = rna_tf32(v1.y);
            }
            *(float2*)&C[(size_t)r * ldc + c]       = v0;
            *(float2*)&C[(size_t)(r + 8) * ldc + c] = v1;
        }
    }
}

// ---------------------------------------------------------------------------
// RNA tf32 rounding pre-pass (vectorized)
// ---------------------------------------------------------------------------
__global__ void __launch_bounds__(256)
round_tf32_kernel(const float4* __restrict__ in, float4* __restrict__ out, int n4)
{
    int i = blockIdx.x * 256 + threadIdx.x;
    if (i < n4) {
        float4 v = in[i];
        v.x = rna_tf32(v.x); v.y = rna_tf32(v.y);
        v.z = rna_tf32(v.z); v.w = rna_tf32(v.w);
        out[i] = v;
    }
}

// ---------------------------------------------------------------------------
// Per-head V transpose: VT[bh][d][k] = V[b*SEQ+k][h*HDIM+d]
// ---------------------------------------------------------------------------
__global__ void __launch_bounds__(256)
transpose_v_kernel(const float* __restrict__ V, float* __restrict__ VT)
{
    __shared__ float t[32][33];
    const int bh = blockIdx.z;
    const int b = bh / HEADS_, h = bh % HEADS_;
    const int k0 = blockIdx.x * 32;
    const int d0 = blockIdx.y * 32;
    const int tx = threadIdx.x & 31;
    const int ty = threadIdx.x >> 5;   // 0..7
    const float* src = V + (size_t)(b * SEQ_) * HIDDEN_ + h * HDIM_;
#pragma unroll
    for (int j = 0; j < 4; ++j)
        t[ty + 8 * j][tx] = src[(size_t)(k0 + ty + 8 * j) * HIDDEN_ + d0 + tx];
    __syncthreads();
    float* dst = VT + (size_t)bh * HDIM_ * SEQ_;
#pragma unroll
    for (int j = 0; j < 4; ++j)
        dst[(size_t)(d0 + ty + 8 * j) * SEQ_ + k0 + tx] = t[tx][ty + 8 * j];
}

// ---------------------------------------------------------------------------
// In-place softmax over 2048 cols: p <- RNA(softmax(raw * temp))
// ---------------------------------------------------------------------------
__global__ void __launch_bounds__(256)
softmax_kernel(float* __restrict__ P, const float* __restrict__ tptr)
{
    __shared__ float red[8];
    __shared__ float bc;

    const size_t row = blockIdx.x;
    float* p = P + row * (size_t)SEQ_;
    const int tid = threadIdx.x;
    const int lane = tid & 31, wid = tid >> 5;
    const float temp = *tptr;

    float v[8];
#pragma unroll
    for (int u = 0; u < 8; ++u) v[u] = p[tid + 256 * u] * temp;

    float m = v[0];
#pragma unroll
    for (int u = 1; u < 8; ++u) m = fmaxf(m, v[u]);
#pragma unroll
    for (int o = 16; o; o >>= 1) m = fmaxf(m, __shfl_xor_sync(0xffffffffu, m, o));
    if (lane == 0) red[wid] = m;
    __syncthreads();
    if (wid == 0) {
        float t = (lane < 8) ? red[lane] : -INFINITY;
#pragma unroll
        for (int o = 16; o; o >>= 1) t = fmaxf(t, __shfl_xor_sync(0xffffffffu, t, o));
        if (lane == 0) bc = t;
    }
    __syncthreads();
    m = bc;

    float s = 0.0f;
#pragma unroll
    for (int u = 0; u < 8; ++u) { v[u] = __expf(v[u] - m); s += v[u]; }
#pragma unroll
    for (int o = 16; o; o >>= 1) s += __shfl_xor_sync(0xffffffffu, s, o);
    __syncthreads();
    if (lane == 0) red[wid] = s;
    __syncthreads();
    if (wid == 0) {
        float t = (lane < 8) ? red[lane] : 0.0f;
#pragma unroll
        for (int o = 16; o; o >>= 1) t += __shfl_xor_sync(0xffffffffu, t, o);
        if (lane == 0) bc = t;
    }
    __syncthreads();
    const float inv = 1.0f / bc;
#pragma unroll
    for (int u = 0; u < 8; ++u) p[tid + 256 * u] = rna_tf32(v[u] * inv);
}

// ---------------------------------------------------------------------------
// Residual + LayerNorm (fp32)
// ---------------------------------------------------------------------------
__global__ void __launch_bounds__(256)
ln_kernel(const float* __restrict__ o, const float* __restrict__ resid,
          const float* __restrict__ gamma, const float* __restrict__ beta,
          float* __restrict__ out)
{
    __shared__ float red1[8], red2[8];
    __shared__ float bmean, binv;

    const size_t row = blockIdx.x;
    const int tid = threadIdx.x;
    const int lane = tid & 31, wid = tid >> 5;
    const float* po = o + row * HIDDEN_;
    const float* pr = resid + row * HIDDEN_;

    float x[4];
    float s = 0.0f, s2 = 0.0f;
#pragma unroll
    for (int u = 0; u < 4; ++u) {
        const int idx = tid + 256 * u;
        x[u] = po[idx] + pr[idx];
        s += x[u];
        s2 += x[u] * x[u];
    }
#pragma unroll
    for (int of = 16; of; of >>= 1) {
        s  += __shfl_xor_sync(0xffffffffu, s,  of);
        s2 += __shfl_xor_sync(0xffffffffu, s2, of);
    }
    if (lane == 0) { red1[wid] = s; red2[wid] = s2; }
    __syncthreads();
    if (wid == 0) {
        float t1 = (lane < 8) ? red1[lane] : 0.0f;
        float t2 = (lane < 8) ? red2[lane] : 0.0f;
#pragma unroll
        for (int of = 16; of; of >>= 1) {
            t1 += __shfl_xor_sync(0xffffffffu, t1, of);
            t2 += __shfl_xor_sync(0xffffffffu, t2, of);
        }
        if (lane == 0) {
            const float mean = t1 * (1.0f / HIDDEN_);
            const float var  = t2 * (1.0f / HIDDEN_) - mean * mean;
            bmean = mean;
            binv  = rsqrtf(var + 1e-5f);
        }
    }
    __syncthreads();
    const float mean = bmean, inv = binv;
#pragma unroll
    for (int u = 0; u < 4; ++u) {
        const int idx = tid + 256 * u;
        out[row * HIDDEN_ + idx] = (x[u] - mean) * inv * gamma[idx] + beta[idx];
    }
}

// ---------------------------------------------------------------------------
// dyn smem: 2 stages * (128 + BN) * 36 floats
static const int DSM_128 = 2 * (128 + 128) * 36 * 4;  // 73728
static const int DSM_64  = 2 * (128 + 64)  * 36 * 4;  // 55296

extern "C" void kernel_launch(void* const* d_in, const int* in_sizes, int n_in,
                              void* d_out, int out_size)
{
    const float* query = (const float*)d_in[0];
    const float* key_  = (const float*)d_in[1];
    const float* value = (const float*)d_in[2];
    const float* Wq = (const float*)d_in[3];
    const float* bq = (const float*)d_in[4];
    const float* Wk = (const float*)d_in[5];
    const float* bk = (const float*)d_in[6];
    const float* Wv = (const float*)d_in[7];
    const float* bv = (const float*)d_in[8];
    const float* Wo = (const float*)d_in[9];
    const float* bo = (const float*)d_in[10];
    const float* gamma = (const float*)d_in[11];
    const float* beta  = (const float*)d_in[12];
    const float* temp  = (const float*)d_in[13];

    cudaFuncSetAttribute(tc_gemm<128, true >, cudaFuncAttributeMaxDynamicSharedMemorySize, DSM_128);
    cudaFuncSetAttribute(tc_gemm<128, false>, cudaFuncAttributeMaxDynamicSharedMemorySize, DSM_128);
    cudaFuncSetAttribute(tc_gemm<64,  true >, cudaFuncAttributeMaxDynamicSharedMemorySize, DSM_64);

    float* out_ln = (float*)d_out;
    float *pQ, *pK, *pV, *pVT, *pCtx, *pO, *pRq, *pRk, *pRv, *pWq, *pWk, *pWv, *pWo, *pP;
    cudaGetSymbolAddress((void**)&pQ,   g_Q);
    cudaGetSymbolAddress((void**)&pK,   g_K);
    cudaGetSymbolAddress((void**)&pV,   g_V);
    cudaGetSymbolAddress((void**)&pVT,  g_VT);
    cudaGetSymbolAddress((void**)&pCtx, g_ctx);
    cudaGetSymbolAddress((void**)&pO,   g_o);
    cudaGetSymbolAddress((void**)&pRq,  g_rq);
    cudaGetSymbolAddress((void**)&pRk,  g_rk);
    cudaGetSymbolAddress((void**)&pRv,  g_rv);
    cudaGetSymbolAddress((void**)&pWq,  g_wq);
    cudaGetSymbolAddress((void**)&pWk,  g_wk);
    cudaGetSymbolAddress((void**)&pWv,  g_wv);
    cudaGetSymbolAddress((void**)&pWo,  g_wo);
    if ((long long)out_size >= LN_N + ATT_N) {
        pP = out_ln + LN_N;           // attn_weights are part of the output
    } else {
        cudaGetSymbolAddress((void**)&pP, g_P);
    }

    const long long sQKV = (long long)SEQ_ * HIDDEN_;
    const long long sPP  = (long long)SEQ_ * SEQ_;

    // --- RNA tf32 pre-rounding of GEMM operands
    {
        const int n4x = (MTOT_ * HIDDEN_) / 4;
        const int n4w = (HIDDEN_ * HIDDEN_) / 4;
        round_tf32_kernel<<<(n4x + 255) / 256, 256>>>((const float4*)query, (float4*)pRq, n4x);
        round_tf32_kernel<<<(n4x + 255) / 256, 256>>>((const float4*)key_,  (float4*)pRk, n4x);
        round_tf32_kernel<<<(n4x + 255) / 256, 256>>>((const float4*)value, (float4*)pRv, n4x);
        round_tf32_kernel<<<(n4w + 255) / 256, 256>>>((const float4*)Wq, (float4*)pWq, n4w);
        round_tf32_kernel<<<(n4w + 255) / 256, 256>>>((const float4*)Wk, (float4*)pWk, n4w);
        round_tf32_kernel<<<(n4w + 255) / 256, 256>>>((const float4*)Wv, (float4*)pWv, n4w);
        round_tf32_kernel<<<(n4w + 255) / 256, 256>>>((const float4*)Wo, (float4*)pWo, n4w);
    }

    // --- Projections: X @ W^T + b -> [4096,1024], outputs RNA-rounded
    {
        dim3 g(HIDDEN_ / 128, MTOT_ / 128, 1);
        tc_gemm<128, true><<<g, 256, DSM_128>>>(pRq, pWq, bq, pQ,
            HIDDEN_, HIDDEN_, HIDDEN_, HIDDEN_, 1, 0,0,0,0,0,0);
        tc_gemm<128, true><<<g, 256, DSM_128>>>(pRk, pWk, bk, pK,
            HIDDEN_, HIDDEN_, HIDDEN_, HIDDEN_, 1, 0,0,0,0,0,0);
        tc_gemm<128, true><<<g, 256, DSM_128>>>(pRv, pWv, bv, pV,
            HIDDEN_, HIDDEN_, HIDDEN_, HIDDEN_, 1, 0,0,0,0,0,0);
    }

    // --- VT: per-head transpose of V
    {
        dim3 g(SEQ_ / 32, HDIM_ / 32, BATCH_ * HEADS_);
        transpose_v_kernel<<<g, 256>>>(pV, pVT);
    }

    // --- Scores: per (b,h): S = Q_h @ K_h^T (raw; temp applied in softmax)
    {
        dim3 g(SEQ_ / 128, SEQ_ / 128, BATCH_ * HEADS_);
        tc_gemm<128, false><<<g, 256, DSM_128>>>(pQ, pK, nullptr, pP,
            HDIM_, HIDDEN_, HIDDEN_, SEQ_, HEADS_,
            sQKV, (long long)HDIM_,
            sQKV, (long long)HDIM_,
            (long long)HEADS_ * sPP, sPP);
    }

    // --- Softmax (in place, *temp, RNA-rounded) -> P (attn_weights output)
    softmax_kernel<<<(unsigned)(BATCH_ * HEADS_ * SEQ_), 256>>>(pP, temp);

    // --- Context: per (b,h): ctx = P @ VT^T  [2048 x 64], K=2048
    {
        dim3 g(1, SEQ_ / 128, BATCH_ * HEADS_);
        tc_gemm<64, true><<<g, 256, DSM_64>>>(pP, pVT, nullptr, pCtx,
            SEQ_, SEQ_, SEQ_, HIDDEN_, HEADS_,
            (long long)HEADS_ * sPP, sPP,
            (long long)HEADS_ * HDIM_ * SEQ_, (long long)HDIM_ * SEQ_,
            sQKV, (long long)HDIM_);
    }

    // --- Output projection: o = ctx @ Wo^T + bo
    {
        dim3 g(HIDDEN_ / 128, MTOT_ / 128, 1);
        tc_gemm<128, false><<<g, 256, DSM_128>>>(pCtx, pWo, bo, pO,
            HIDDEN_, HIDDEN_, HIDDEN_, HIDDEN_, 1, 0,0,0,0,0,0);
    }

    // --- Residual + LayerNorm
    ln_kernel<<<(unsigned)MTOT_, 256>>>(pO, query, gamma, beta, out_ln);
}